// round 8
// baseline (speedup 1.0000x reference)
#include <cuda_runtime.h>
#include <cstdint>

// ---------------------------------------------------------------------------
// DualOrthogonalAttention, round 8: 3xTF32 MMA, 1024 threads, float4 cp.async
// weights (flat stride-65 + alignment pad), feature hi/lo pairs in smem,
// in-place softmax (A aliases scores), 7 barriers/head.
// ---------------------------------------------------------------------------

#define BSZ 1024
#define S 62
#define DIM 65
#define H 10
#define NT 1024

#define SP 152      // pairs stride (floats): mod 32 = 24 -> conflict-free
#define SQ 76       // plain Q/K/score stride: mod 32 = 12 -> conflict-free
#define WB 4240     // flat weight buffer floats (4225 + pad + slack)

#define OFF_FNP 0
#define OFF_FRP (OFF_FNP + 64*SP)
#define OFF_Q   (OFF_FRP + 64*SP)
#define OFF_K   (OFF_Q + 64*SQ)
#define OFF_S1  (OFF_K + 64*SQ)
#define OFF_S2  (OFF_S1 + 64*SQ)
#define OFF_W   (OFF_S2 + 64*SQ)
#define OFF_B   (OFF_W + 4*WB)
#define OFF_G1  (OFF_B + 4*68)
#define OFF_G2  (OFF_G1 + 68)
#define OFF_MEAN (OFF_G2 + 68)
#define OFF_WARP (OFF_MEAN + 132)
#define SMEM_FLOATS (OFF_WARP + 36)   // 56448 floats = 220.5 KB

__device__ float g_norms[BSZ * H];

// ---------------------------------------------------------------------------
__device__ __forceinline__ void cp_async16(uint32_t dst, const float4* src) {
    asm volatile("cp.async.cg.shared.global [%0], [%1], 16;\n" :: "r"(dst), "l"(src));
}
__device__ __forceinline__ void cp_async4(uint32_t dst, const float* src) {
    asm volatile("cp.async.ca.shared.global [%0], [%1], 4;\n" :: "r"(dst), "l"(src));
}
__device__ __forceinline__ void cp_commit() {
    asm volatile("cp.async.commit_group;\n" ::);
}
__device__ __forceinline__ void cp_wait0() {
    asm volatile("cp.async.wait_group 0;\n" ::);
}

__device__ __forceinline__ uint32_t f2tf32(float x) {
    uint32_t r;
    asm("cvt.rna.tf32.f32 %0, %1;\n" : "=r"(r) : "f"(x));
    return r;
}

__device__ __forceinline__ void mma8(float* c, uint32_t a0, uint32_t a1,
                                     uint32_t a2, uint32_t a3,
                                     uint32_t b0, uint32_t b1) {
    asm volatile(
        "mma.sync.aligned.m16n8k8.row.col.f32.tf32.tf32.f32 "
        "{%0,%1,%2,%3}, {%4,%5,%6,%7}, {%8,%9}, {%0,%1,%2,%3};\n"
        : "+f"(c[0]), "+f"(c[1]), "+f"(c[2]), "+f"(c[3])
        : "r"(a0), "r"(a1), "r"(a2), "r"(a3), "r"(b0), "r"(b1));
}

// prefetch all 4 head-weight tiles (flat, float4) + 4 bias slices; one group
__device__ __forceinline__ void prefetch_head(
    const float* __restrict__ wq1, const float* __restrict__ wk1,
    const float* __restrict__ wq2, const float* __restrict__ wk2,
    const float* __restrict__ b1, const float* __restrict__ b2,
    const float* __restrict__ b3, const float* __restrict__ b4,
    int h, float* sW, float* sB)
{
    const int pad = h & 3;                          // (h*4225) % 4
    const int n4 = (DIM * DIM + pad + 3) >> 2;
    const float* ws[4] = { wq1, wk1, wq2, wk2 };
    const float* bs[4] = { b1, b2, b3, b4 };
#pragma unroll
    for (int i = 0; i < 4; i++) {
        const float4* s4 = (const float4*)(ws[i] + h * DIM * DIM - pad);
        uint32_t dst = (uint32_t)__cvta_generic_to_shared(sW + i * WB);
        for (int j = threadIdx.x; j < n4; j += NT)
            cp_async16(dst + 16u * j, s4 + j);
        if (threadIdx.x < DIM) {
            uint32_t bd = (uint32_t)__cvta_generic_to_shared(sB + i * 68 + threadIdx.x);
            cp_async4(bd, bs[i] + h * DIM + threadIdx.x);
        }
    }
    cp_commit();
}

// ---------------------------------------------------------------------------
// AMODE: 0 = hi/lo pairs (stride SP), 1 = plain 3x (stride SQ), 2 = plain hi-only
// BMODE: 0 = flat W, transposed role, 3x   1 = plain BT (SQ), 3x
//        2 = plain BT (SQ), hi-only        3 = hi/lo pairs, B-natural (SP)
// EPI:   0 proj (bias, zero col>=65, smem SQ)  1 logits (scale, smem SQ)
//        2 gmem gated store                    3 loss sum
// ---------------------------------------------------------------------------
template <int EPI, int AMODE, int BMODE, int NS, int KS>
__device__ __forceinline__ float mma_tile(
    const float* __restrict__ A, const float* __restrict__ B, const int bpad,
    const int mt, const int n0,
    float* __restrict__ C, const float* __restrict__ aux, const float scale)
{
    const int lane = threadIdx.x & 31;
    const int lr = lane >> 2;
    const int lc = lane & 3;
    constexpr bool PREC = (AMODE != 2);

    float acc[NS][4];
#pragma unroll
    for (int ns = 0; ns < NS; ns++) {
        acc[ns][0] = 0.f; acc[ns][1] = 0.f; acc[ns][2] = 0.f; acc[ns][3] = 0.f;
    }

    const float* Ap = (AMODE == 0) ? (A + (mt * 16 + lr) * SP + 2 * lc)
                                   : (A + (mt * 16 + lr) * SQ + lc);

#pragma unroll
    for (int ks = 0; ks < KS; ks++) {
        const int k8 = ks * 8;
        uint32_t ahi[4], alo[4];
        if (AMODE == 0) {
            const float2 p0 = *(const float2*)(Ap + 2 * k8);
            const float2 p1 = *(const float2*)(Ap + 8 * SP + 2 * k8);
            const float2 p2 = *(const float2*)(Ap + 2 * k8 + 8);
            const float2 p3 = *(const float2*)(Ap + 8 * SP + 2 * k8 + 8);
            ahi[0] = __float_as_uint(p0.x); alo[0] = __float_as_uint(p0.y);
            ahi[1] = __float_as_uint(p1.x); alo[1] = __float_as_uint(p1.y);
            ahi[2] = __float_as_uint(p2.x); alo[2] = __float_as_uint(p2.y);
            ahi[3] = __float_as_uint(p3.x); alo[3] = __float_as_uint(p3.y);
        } else {
            float af[4];
            af[0] = Ap[k8];
            af[1] = Ap[8 * SQ + k8];
            af[2] = Ap[k8 + 4];
            af[3] = Ap[8 * SQ + k8 + 4];
#pragma unroll
            for (int i = 0; i < 4; i++) {
                ahi[i] = f2tf32(af[i]);
                if (PREC) alo[i] = f2tf32(af[i] - __uint_as_float(ahi[i]));
            }
        }
#pragma unroll
        for (int ns = 0; ns < NS; ns++) {
            const int nn = n0 + ns * 8;
            uint32_t bhi0, bhi1, blo0, blo1;
            if (BMODE == 0) {
                const float* Bp = B + bpad + (nn + lr) * DIM + lc;
                const float bf0 = Bp[k8];
                const float bf1 = Bp[k8 + 4];
                bhi0 = f2tf32(bf0); blo0 = f2tf32(bf0 - __uint_as_float(bhi0));
                bhi1 = f2tf32(bf1); blo1 = f2tf32(bf1 - __uint_as_float(bhi1));
            } else if (BMODE == 1 || BMODE == 2) {
                const float* Bp = B + (nn + lr) * SQ + lc;
                const float bf0 = Bp[k8];
                const float bf1 = Bp[k8 + 4];
                bhi0 = f2tf32(bf0);
                bhi1 = f2tf32(bf1);
                if (BMODE == 1) {
                    blo0 = f2tf32(bf0 - __uint_as_float(bhi0));
                    blo1 = f2tf32(bf1 - __uint_as_float(bhi1));
                }
            } else {  // BMODE 3: pairs, B-natural
                const float* Bp = B + lc * SP + 2 * (nn + lr);
                const float2 q0 = *(const float2*)(Bp + k8 * SP);
                const float2 q1 = *(const float2*)(Bp + (k8 + 4) * SP);
                bhi0 = __float_as_uint(q0.x); blo0 = __float_as_uint(q0.y);
                bhi1 = __float_as_uint(q1.x); blo1 = __float_as_uint(q1.y);
            }
            mma8(acc[ns], ahi[0], ahi[1], ahi[2], ahi[3], bhi0, bhi1);
            if (PREC && BMODE != 2) {
                mma8(acc[ns], alo[0], alo[1], alo[2], alo[3], bhi0, bhi1);
                mma8(acc[ns], ahi[0], ahi[1], ahi[2], ahi[3], blo0, blo1);
            }
        }
    }

    float ss = 0.f;
    const int r0 = mt * 16 + lr;   // <= 55
    const int rr = r0 + 8;         // <= 63

#pragma unroll
    for (int ns = 0; ns < NS; ns++) {
        const int col = n0 + ns * 8 + 2 * lc;
        if (EPI == 0) {
            float v0 = 0.f, v1 = 0.f, w0 = 0.f, w1 = 0.f;
            if (col < DIM)     { const float bb = aux[col];     v0 = acc[ns][0] + bb; w0 = acc[ns][2] + bb; }
            if (col + 1 < DIM) { const float bb = aux[col + 1]; v1 = acc[ns][1] + bb; w1 = acc[ns][3] + bb; }
            *(float2*)(C + r0 * SQ + col) = make_float2(v0, v1);
            *(float2*)(C + rr * SQ + col) = make_float2(w0, w1);
        } else if (EPI == 1) {
            *(float2*)(C + r0 * SQ + col) = make_float2(acc[ns][0] * scale, acc[ns][1] * scale);
            *(float2*)(C + rr * SQ + col) = make_float2(acc[ns][2] * scale, acc[ns][3] * scale);
        } else if (EPI == 2) {
            if (col < 64) {
                const float g0 = aux[col], g1 = aux[col + 1];
                C[r0 * DIM + col]     = g0 * acc[ns][0];
                C[r0 * DIM + col + 1] = g1 * acc[ns][1];
                if (rr < S) {
                    C[rr * DIM + col]     = g0 * acc[ns][2];
                    C[rr * DIM + col + 1] = g1 * acc[ns][3];
                }
            } else if (col == 64) {
                const float g0 = aux[64];
                C[r0 * DIM + 64] = g0 * acc[ns][0];
                if (rr < S) C[rr * DIM + 64] = g0 * acc[ns][2];
            }
        } else {  // loss
            if (col < S) {
                const float d = acc[ns][0] - ((r0 == col) ? 1.f : 0.f);
                ss = fmaf(d, d, ss);
            }
            if (col + 1 < S) {
                const float d = acc[ns][1] - ((r0 == col + 1) ? 1.f : 0.f);
                ss = fmaf(d, d, ss);
            }
            if (rr < S) {
                if (col < S) {
                    const float d = acc[ns][2] - ((rr == col) ? 1.f : 0.f);
                    ss = fmaf(d, d, ss);
                }
                if (col + 1 < S) {
                    const float d = acc[ns][3] - ((rr == col + 1) ? 1.f : 0.f);
                    ss = fmaf(d, d, ss);
                }
            }
        }
    }
    return ss;
}

// wide (N=65->72) tile dispatch: g<7 -> 8 cols, g==7 -> 16 cols (56..71)
template <int EPI, int AMODE, int BMODE, int KS>
__device__ __forceinline__ float wide_tile(
    const float* A, const float* B, int bpad, int mt, int g,
    float* C, const float* aux)
{
    if (g < 7)
        return mma_tile<EPI, AMODE, BMODE, 1, KS>(A, B, bpad, mt, g * 8, C, aux, 0.f);
    return mma_tile<EPI, AMODE, BMODE, 2, KS>(A, B, bpad, mt, 56, C, aux, 0.f);
}

// in-place row softmax over sS [62 x SQ]; zeroes cols 62,63
__device__ __forceinline__ void softmax62(float* __restrict__ sS_) {
    const int w = threadIdx.x >> 5;
    const int lane = threadIdx.x & 31;
    const bool ok1 = (lane + 32) < S;
    for (int r = w; r < S; r += 32) {
        float* row = sS_ + r * SQ;
        const float v0 = row[lane];
        const float v1 = ok1 ? row[lane + 32] : -1e30f;
        float m = fmaxf(v0, v1);
#pragma unroll
        for (int off = 16; off; off >>= 1) m = fmaxf(m, __shfl_xor_sync(0xffffffffu, m, off));
        const float e0 = __expf(v0 - m);
        const float e1 = ok1 ? __expf(v1 - m) : 0.f;
        float s = e0 + e1;
#pragma unroll
        for (int off = 16; off; off >>= 1) s += __shfl_xor_sync(0xffffffffu, s, off);
        const float inv = 1.0f / s;
        row[lane] = e0 * inv;
        row[lane + 32] = ok1 ? (e1 * inv) : 0.f;
    }
}

__global__ void __launch_bounds__(NT, 1)
fused_kernel(const float* __restrict__ Fn, const float* __restrict__ Fr,
             const float* __restrict__ Wq1, const float* __restrict__ bq1,
             const float* __restrict__ Wk1, const float* __restrict__ bk1,
             const float* __restrict__ Wq2, const float* __restrict__ bq2,
             const float* __restrict__ Wk2, const float* __restrict__ bk2,
             const float* __restrict__ Wg, const float* __restrict__ bg,
             float* __restrict__ out)
{
    extern __shared__ float sm[];
    const int tid = threadIdx.x;
    const int b = blockIdx.x;
    const int w = tid >> 5;
    const int mt = w >> 3;     // 0..3 row tile
    const int g  = w & 7;      // 0..7 col group

    float* sFnP = sm + OFF_FNP;
    float* sFrP = sm + OFF_FRP;
    float* sQ   = sm + OFF_Q;
    float* sK   = sm + OFF_K;
    float* sS1  = sm + OFF_S1;   // becomes A1 in place
    float* sS2  = sm + OFF_S2;   // becomes A2 in place
    float* sW   = sm + OFF_W;
    float* sB   = sm + OFF_B;
    float* sG1  = sm + OFF_G1;
    float* sG2  = sm + OFF_G2;
    float* smean = sm + OFF_MEAN;
    float* swarp = sm + OFF_WARP;

    // zero all smem (pads become hard zeros)
    {
        float4* z = (float4*)sm;
        const float4 z4 = make_float4(0.f, 0.f, 0.f, 0.f);
        for (int i = tid; i < SMEM_FLOATS / 4; i += NT) z[i] = z4;
    }
    __syncthreads();

    prefetch_head(Wq1, Wk1, Wq2, Wk2, bq1, bk1, bq2, bk2, 0, sW, sB);

    // stage features as hi/lo tf32 pairs
    for (int idx = tid; idx < S * DIM; idx += NT) {
        const int i = idx / DIM;
        const int d = idx - i * DIM;
        const float vn = Fn[(size_t)b * S * DIM + idx];
        const float vr = Fr[(size_t)b * S * DIM + idx];
        const uint32_t nh = f2tf32(vn);
        const uint32_t rh = f2tf32(vr);
        *(float2*)(sFnP + i * SP + 2 * d) =
            make_float2(__uint_as_float(nh), __uint_as_float(f2tf32(vn - __uint_as_float(nh))));
        *(float2*)(sFrP + i * SP + 2 * d) =
            make_float2(__uint_as_float(rh), __uint_as_float(f2tf32(vr - __uint_as_float(rh))));
    }
    __syncthreads();

    // gate
    if (tid < 2 * DIM) {
        const int d = (tid < DIM) ? tid : tid - DIM;
        const float* src = (tid < DIM) ? sFnP : sFrP;
        float s = 0.f;
        for (int i = 0; i < S; i++) {
            const float2 p = *(const float2*)(src + i * SP + 2 * d);
            s += p.x + p.y;
        }
        smean[tid] = s * (1.0f / (float)S);
    }
    __syncthreads();
    if (tid < DIM) {
        float acc = bg[tid];
        const float* wr = Wg + tid * 2 * DIM;
#pragma unroll 10
        for (int c = 0; c < 2 * DIM; c++) acc = fmaf(wr[c], smean[c], acc);
        const float gg = 1.0f / (1.0f + __expf(-acc));
        sG1[tid] = gg;
        sG2[tid] = 1.0f - gg;
    }

    const float scale = rsqrtf((float)DIM);

    for (int h = 0; h < H; h++) {
        const int pad = h & 3;
        float* o1 = out + ((size_t)(b * H + h) * 124) * DIM;
        float* o2 = o1 + (size_t)S * DIM;

        // W ready (also guards Q/K/S1/S2 reuse)
        cp_wait0();
        __syncthreads();

        // A: dir1 projections  Q = Fn@Wq1^T+b, K = Fr@Wk1^T+b
        wide_tile<0, 0, 0, 9>(sFnP, sW + 0 * WB, pad, mt, g, sQ, sB + 0 * 68);
        wide_tile<0, 0, 0, 9>(sFrP, sW + 1 * WB, pad, mt, g, sK, sB + 1 * 68);
        __syncthreads();

        // B: logits1 -> S1
        mma_tile<1, 1, 1, 1, 9>(sQ, sK, 0, mt, g * 8, sS1, 0, scale);
        __syncthreads();

        // C: softmax1 (in place) + dir2 projections (reuse Q/K)
        softmax62(sS1);
        wide_tile<0, 0, 0, 9>(sFrP, sW + 2 * WB, pad, mt, g, sQ, sB + 2 * 68);
        wide_tile<0, 0, 0, 9>(sFnP, sW + 3 * WB, pad, mt, g, sK, sB + 3 * 68);
        __syncthreads();

        // prefetch next head's weights (all 4 consumed)
        if (h + 1 < H)
            prefetch_head(Wq1, Wk1, Wq2, Wk2, bq1, bk1, bq2, bk2, h + 1, sW, sB);

        // D: logits2 -> S2
        mma_tile<1, 1, 1, 1, 9>(sQ, sK, 0, mt, g * 8, sS2, 0, scale);
        __syncthreads();

        // E: softmax2
        softmax62(sS2);
        __syncthreads();

        // F: loss gram (single-pass) + gated outputs
        float ss = mma_tile<3, 2, 2, 1, 8>(sS1, sS2, 0, mt, g * 8, (float*)0, 0, 0.f);
        wide_tile<2, 1, 3, 8>(sS1, sFrP, 0, mt, g, o1, sG1);
        wide_tile<2, 1, 3, 8>(sS2, sFnP, 0, mt, g, o2, sG2);
#pragma unroll
        for (int off = 16; off; off >>= 1) ss += __shfl_xor_sync(0xffffffffu, ss, off);
        if ((tid & 31) == 0) swarp[w] = ss;
        __syncthreads();
        if (tid == 0) {
            float t = 0.f;
#pragma unroll
            for (int ww = 0; ww < 32; ww++) t += swarp[ww];
            g_norms[b * H + h] = sqrtf(t);
        }
    }
}

__global__ void loss_kernel(float* __restrict__ out_loss)
{
    __shared__ float ws[8];
    const int tid = threadIdx.x;
    float s = 0.f;
    for (int i = tid; i < BSZ * H; i += 256) s += g_norms[i];
#pragma unroll
    for (int off = 16; off; off >>= 1) s += __shfl_xor_sync(0xffffffffu, s, off);
    if ((tid & 31) == 0) ws[tid >> 5] = s;
    __syncthreads();
    if (tid == 0) {
        float t = 0.f;
#pragma unroll
        for (int w = 0; w < 8; w++) t += ws[w];
        *out_loss = t / (float)(BSZ * H);
    }
}

extern "C" void kernel_launch(void* const* d_in, const int* in_sizes, int n_in,
                              void* d_out, int out_size)
{
    const float* Fn  = (const float*)d_in[0];
    const float* Fr  = (const float*)d_in[1];
    const float* Wq1 = (const float*)d_in[2];
    const float* bq1 = (const float*)d_in[3];
    const float* Wk1 = (const float*)d_in[4];
    const float* bk1 = (const float*)d_in[5];
    const float* Wq2 = (const float*)d_in[6];
    const float* bq2 = (const float*)d_in[7];
    const float* Wk2 = (const float*)d_in[8];
    const float* bk2 = (const float*)d_in[9];
    const float* Wg  = (const float*)d_in[10];
    const float* bg  = (const float*)d_in[11];
    float* out = (float*)d_out;

    const int smem_bytes = SMEM_FLOATS * (int)sizeof(float);
    cudaFuncSetAttribute(fused_kernel, cudaFuncAttributeMaxDynamicSharedMemorySize, smem_bytes);
    fused_kernel<<<BSZ, NT, smem_bytes>>>(Fn, Fr, Wq1, bq1, Wk1, bk1,
                                          Wq2, bq2, Wk2, bk2, Wg, bg, out);
    loss_kernel<<<1, 256>>>(out + (size_t)out_size - 1);
}

// round 9
// speedup vs baseline: 1.0007x; 1.0007x over previous
#include <cuda_runtime.h>
#include <cstdint>

// ---------------------------------------------------------------------------
// DualOrthogonalAttention, round 8: 3xTF32 MMA, 1024 threads, float4 cp.async
// weights (flat stride-65 + alignment pad), feature hi/lo pairs in smem,
// in-place softmax (A aliases scores), 7 barriers/head.
// ---------------------------------------------------------------------------

#define BSZ 1024
#define S 62
#define DIM 65
#define H 10
#define NT 1024

#define SP 152      // pairs stride (floats): mod 32 = 24 -> conflict-free
#define SQ 76       // plain Q/K/score stride: mod 32 = 12 -> conflict-free
#define WB 4240     // flat weight buffer floats (4225 + pad + slack)

#define OFF_FNP 0
#define OFF_FRP (OFF_FNP + 64*SP)
#define OFF_Q   (OFF_FRP + 64*SP)
#define OFF_K   (OFF_Q + 64*SQ)
#define OFF_S1  (OFF_K + 64*SQ)
#define OFF_S2  (OFF_S1 + 64*SQ)
#define OFF_W   (OFF_S2 + 64*SQ)
#define OFF_B   (OFF_W + 4*WB)
#define OFF_G1  (OFF_B + 4*68)
#define OFF_G2  (OFF_G1 + 68)
#define OFF_MEAN (OFF_G2 + 68)
#define OFF_WARP (OFF_MEAN + 132)
#define SMEM_FLOATS (OFF_WARP + 36)   // 56448 floats = 220.5 KB

__device__ float g_norms[BSZ * H];

// ---------------------------------------------------------------------------
__device__ __forceinline__ void cp_async16(uint32_t dst, const float4* src) {
    asm volatile("cp.async.cg.shared.global [%0], [%1], 16;\n" :: "r"(dst), "l"(src));
}
__device__ __forceinline__ void cp_async4(uint32_t dst, const float* src) {
    asm volatile("cp.async.ca.shared.global [%0], [%1], 4;\n" :: "r"(dst), "l"(src));
}
__device__ __forceinline__ void cp_commit() {
    asm volatile("cp.async.commit_group;\n" ::);
}
__device__ __forceinline__ void cp_wait0() {
    asm volatile("cp.async.wait_group 0;\n" ::);
}

__device__ __forceinline__ uint32_t f2tf32(float x) {
    uint32_t r;
    asm("cvt.rna.tf32.f32 %0, %1;\n" : "=r"(r) : "f"(x));
    return r;
}

__device__ __forceinline__ void mma8(float* c, uint32_t a0, uint32_t a1,
                                     uint32_t a2, uint32_t a3,
                                     uint32_t b0, uint32_t b1) {
    asm volatile(
        "mma.sync.aligned.m16n8k8.row.col.f32.tf32.tf32.f32 "
        "{%0,%1,%2,%3}, {%4,%5,%6,%7}, {%8,%9}, {%0,%1,%2,%3};\n"
        : "+f"(c[0]), "+f"(c[1]), "+f"(c[2]), "+f"(c[3])
        : "r"(a0), "r"(a1), "r"(a2), "r"(a3), "r"(b0), "r"(b1));
}

// prefetch all 4 head-weight tiles (flat, float4) + 4 bias slices; one group
__device__ __forceinline__ void prefetch_head(
    const float* __restrict__ wq1, const float* __restrict__ wk1,
    const float* __restrict__ wq2, const float* __restrict__ wk2,
    const float* __restrict__ b1, const float* __restrict__ b2,
    const float* __restrict__ b3, const float* __restrict__ b4,
    int h, float* sW, float* sB)
{
    const int pad = h & 3;                          // (h*4225) % 4
    const int n4 = (DIM * DIM + pad + 3) >> 2;
    const float* ws[4] = { wq1, wk1, wq2, wk2 };
    const float* bs[4] = { b1, b2, b3, b4 };
#pragma unroll
    for (int i = 0; i < 4; i++) {
        const float4* s4 = (const float4*)(ws[i] + h * DIM * DIM - pad);
        uint32_t dst = (uint32_t)__cvta_generic_to_shared(sW + i * WB);
        for (int j = threadIdx.x; j < n4; j += NT)
            cp_async16(dst + 16u * j, s4 + j);
        if (threadIdx.x < DIM) {
            uint32_t bd = (uint32_t)__cvta_generic_to_shared(sB + i * 68 + threadIdx.x);
            cp_async4(bd, bs[i] + h * DIM + threadIdx.x);
        }
    }
    cp_commit();
}

// ---------------------------------------------------------------------------
// AMODE: 0 = hi/lo pairs (stride SP), 1 = plain 3x (stride SQ), 2 = plain hi-only
// BMODE: 0 = flat W, transposed role, 3x   1 = plain BT (SQ), 3x
//        2 = plain BT (SQ), hi-only        3 = hi/lo pairs, B-natural (SP)
// EPI:   0 proj (bias, zero col>=65, smem SQ)  1 logits (scale, smem SQ)
//        2 gmem gated store                    3 loss sum
// ---------------------------------------------------------------------------
template <int EPI, int AMODE, int BMODE, int NS, int KS>
__device__ __forceinline__ float mma_tile(
    const float* __restrict__ A, const float* __restrict__ B, const int bpad,
    const int mt, const int n0,
    float* __restrict__ C, const float* __restrict__ aux, const float scale)
{
    const int lane = threadIdx.x & 31;
    const int lr = lane >> 2;
    const int lc = lane & 3;
    constexpr bool PREC = (AMODE != 2);

    float acc[NS][4];
#pragma unroll
    for (int ns = 0; ns < NS; ns++) {
        acc[ns][0] = 0.f; acc[ns][1] = 0.f; acc[ns][2] = 0.f; acc[ns][3] = 0.f;
    }

    const float* Ap = (AMODE == 0) ? (A + (mt * 16 + lr) * SP + 2 * lc)
                                   : (A + (mt * 16 + lr) * SQ + lc);

#pragma unroll
    for (int ks = 0; ks < KS; ks++) {
        const int k8 = ks * 8;
        uint32_t ahi[4], alo[4];
        if (AMODE == 0) {
            const float2 p0 = *(const float2*)(Ap + 2 * k8);
            const float2 p1 = *(const float2*)(Ap + 8 * SP + 2 * k8);
            const float2 p2 = *(const float2*)(Ap + 2 * k8 + 8);
            const float2 p3 = *(const float2*)(Ap + 8 * SP + 2 * k8 + 8);
            ahi[0] = __float_as_uint(p0.x); alo[0] = __float_as_uint(p0.y);
            ahi[1] = __float_as_uint(p1.x); alo[1] = __float_as_uint(p1.y);
            ahi[2] = __float_as_uint(p2.x); alo[2] = __float_as_uint(p2.y);
            ahi[3] = __float_as_uint(p3.x); alo[3] = __float_as_uint(p3.y);
        } else {
            float af[4];
            af[0] = Ap[k8];
            af[1] = Ap[8 * SQ + k8];
            af[2] = Ap[k8 + 4];
            af[3] = Ap[8 * SQ + k8 + 4];
#pragma unroll
            for (int i = 0; i < 4; i++) {
                ahi[i] = f2tf32(af[i]);
                if (PREC) alo[i] = f2tf32(af[i] - __uint_as_float(ahi[i]));
            }
        }
#pragma unroll
        for (int ns = 0; ns < NS; ns++) {
            const int nn = n0 + ns * 8;
            uint32_t bhi0, bhi1, blo0, blo1;
            if (BMODE == 0) {
                const float* Bp = B + bpad + (nn + lr) * DIM + lc;
                const float bf0 = Bp[k8];
                const float bf1 = Bp[k8 + 4];
                bhi0 = f2tf32(bf0); blo0 = f2tf32(bf0 - __uint_as_float(bhi0));
                bhi1 = f2tf32(bf1); blo1 = f2tf32(bf1 - __uint_as_float(bhi1));
            } else if (BMODE == 1 || BMODE == 2) {
                const float* Bp = B + (nn + lr) * SQ + lc;
                const float bf0 = Bp[k8];
                const float bf1 = Bp[k8 + 4];
                bhi0 = f2tf32(bf0);
                bhi1 = f2tf32(bf1);
                if (BMODE == 1) {
                    blo0 = f2tf32(bf0 - __uint_as_float(bhi0));
                    blo1 = f2tf32(bf1 - __uint_as_float(bhi1));
                }
            } else {  // BMODE 3: pairs, B-natural
                const float* Bp = B + lc * SP + 2 * (nn + lr);
                const float2 q0 = *(const float2*)(Bp + k8 * SP);
                const float2 q1 = *(const float2*)(Bp + (k8 + 4) * SP);
                bhi0 = __float_as_uint(q0.x); blo0 = __float_as_uint(q0.y);
                bhi1 = __float_as_uint(q1.x); blo1 = __float_as_uint(q1.y);
            }
            mma8(acc[ns], ahi[0], ahi[1], ahi[2], ahi[3], bhi0, bhi1);
            if (PREC && BMODE != 2) {
                mma8(acc[ns], alo[0], alo[1], alo[2], alo[3], bhi0, bhi1);
                mma8(acc[ns], ahi[0], ahi[1], ahi[2], ahi[3], blo0, blo1);
            }
        }
    }

    float ss = 0.f;
    const int r0 = mt * 16 + lr;   // <= 55
    const int rr = r0 + 8;         // <= 63

#pragma unroll
    for (int ns = 0; ns < NS; ns++) {
        const int col = n0 + ns * 8 + 2 * lc;
        if (EPI == 0) {
            float v0 = 0.f, v1 = 0.f, w0 = 0.f, w1 = 0.f;
            if (col < DIM)     { const float bb = aux[col];     v0 = acc[ns][0] + bb; w0 = acc[ns][2] + bb; }
            if (col + 1 < DIM) { const float bb = aux[col + 1]; v1 = acc[ns][1] + bb; w1 = acc[ns][3] + bb; }
            *(float2*)(C + r0 * SQ + col) = make_float2(v0, v1);
            *(float2*)(C + rr * SQ + col) = make_float2(w0, w1);
        } else if (EPI == 1) {
            *(float2*)(C + r0 * SQ + col) = make_float2(acc[ns][0] * scale, acc[ns][1] * scale);
            *(float2*)(C + rr * SQ + col) = make_float2(acc[ns][2] * scale, acc[ns][3] * scale);
        } else if (EPI == 2) {
            if (col < 64) {
                const float g0 = aux[col], g1 = aux[col + 1];
                C[r0 * DIM + col]     = g0 * acc[ns][0];
                C[r0 * DIM + col + 1] = g1 * acc[ns][1];
                if (rr < S) {
                    C[rr * DIM + col]     = g0 * acc[ns][2];
                    C[rr * DIM + col + 1] = g1 * acc[ns][3];
                }
            } else if (col == 64) {
                const float g0 = aux[64];
                C[r0 * DIM + 64] = g0 * acc[ns][0];
                if (rr < S) C[rr * DIM + 64] = g0 * acc[ns][2];
            }
        } else {  // loss
            if (col < S) {
                const float d = acc[ns][0] - ((r0 == col) ? 1.f : 0.f);
                ss = fmaf(d, d, ss);
            }
            if (col + 1 < S) {
                const float d = acc[ns][1] - ((r0 == col + 1) ? 1.f : 0.f);
                ss = fmaf(d, d, ss);
            }
            if (rr < S) {
                if (col < S) {
                    const float d = acc[ns][2] - ((rr == col) ? 1.f : 0.f);
                    ss = fmaf(d, d, ss);
                }
                if (col + 1 < S) {
                    const float d = acc[ns][3] - ((rr == col + 1) ? 1.f : 0.f);
                    ss = fmaf(d, d, ss);
                }
            }
        }
    }
    return ss;
}

// wide (N=65->72) tile dispatch: g<7 -> 8 cols, g==7 -> 16 cols (56..71)
template <int EPI, int AMODE, int BMODE, int KS>
__device__ __forceinline__ float wide_tile(
    const float* A, const float* B, int bpad, int mt, int g,
    float* C, const float* aux)
{
    if (g < 7)
        return mma_tile<EPI, AMODE, BMODE, 1, KS>(A, B, bpad, mt, g * 8, C, aux, 0.f);
    return mma_tile<EPI, AMODE, BMODE, 2, KS>(A, B, bpad, mt, 56, C, aux, 0.f);
}

// in-place row softmax over sS [62 x SQ]; zeroes cols 62,63
__device__ __forceinline__ void softmax62(float* __restrict__ sS_) {
    const int w = threadIdx.x >> 5;
    const int lane = threadIdx.x & 31;
    const bool ok1 = (lane + 32) < S;
    for (int r = w; r < S; r += 32) {
        float* row = sS_ + r * SQ;
        const float v0 = row[lane];
        const float v1 = ok1 ? row[lane + 32] : -1e30f;
        float m = fmaxf(v0, v1);
#pragma unroll
        for (int off = 16; off; off >>= 1) m = fmaxf(m, __shfl_xor_sync(0xffffffffu, m, off));
        const float e0 = __expf(v0 - m);
        const float e1 = ok1 ? __expf(v1 - m) : 0.f;
        float s = e0 + e1;
#pragma unroll
        for (int off = 16; off; off >>= 1) s += __shfl_xor_sync(0xffffffffu, s, off);
        const float inv = 1.0f / s;
        row[lane] = e0 * inv;
        row[lane + 32] = ok1 ? (e1 * inv) : 0.f;
    }
}

__global__ void __launch_bounds__(NT, 1)
fused_kernel(const float* __restrict__ Fn, const float* __restrict__ Fr,
             const float* __restrict__ Wq1, const float* __restrict__ bq1,
             const float* __restrict__ Wk1, const float* __restrict__ bk1,
             const float* __restrict__ Wq2, const float* __restrict__ bq2,
             const float* __restrict__ Wk2, const float* __restrict__ bk2,
             const float* __restrict__ Wg, const float* __restrict__ bg,
             float* __restrict__ out)
{
    extern __shared__ float sm[];
    const int tid = threadIdx.x;
    const int b = blockIdx.x;
    const int w = tid >> 5;
    const int mt = w >> 3;     // 0..3 row tile
    const int g  = w & 7;      // 0..7 col group

    float* sFnP = sm + OFF_FNP;
    float* sFrP = sm + OFF_FRP;
    float* sQ   = sm + OFF_Q;
    float* sK   = sm + OFF_K;
    float* sS1  = sm + OFF_S1;   // becomes A1 in place
    float* sS2  = sm + OFF_S2;   // becomes A2 in place
    float* sW   = sm + OFF_W;
    float* sB   = sm + OFF_B;
    float* sG1  = sm + OFF_G1;
    float* sG2  = sm + OFF_G2;
    float* smean = sm + OFF_MEAN;
    float* swarp = sm + OFF_WARP;

    // zero all smem (pads become hard zeros)
    {
        float4* z = (float4*)sm;
        const float4 z4 = make_float4(0.f, 0.f, 0.f, 0.f);
        for (int i = tid; i < SMEM_FLOATS / 4; i += NT) z[i] = z4;
    }
    __syncthreads();

    prefetch_head(Wq1, Wk1, Wq2, Wk2, bq1, bk1, bq2, bk2, 0, sW, sB);

    // stage features as hi/lo tf32 pairs
    for (int idx = tid; idx < S * DIM; idx += NT) {
        const int i = idx / DIM;
        const int d = idx - i * DIM;
        const float vn = Fn[(size_t)b * S * DIM + idx];
        const float vr = Fr[(size_t)b * S * DIM + idx];
        const uint32_t nh = f2tf32(vn);
        const uint32_t rh = f2tf32(vr);
        *(float2*)(sFnP + i * SP + 2 * d) =
            make_float2(__uint_as_float(nh), __uint_as_float(f2tf32(vn - __uint_as_float(nh))));
        *(float2*)(sFrP + i * SP + 2 * d) =
            make_float2(__uint_as_float(rh), __uint_as_float(f2tf32(vr - __uint_as_float(rh))));
    }
    __syncthreads();

    // gate
    if (tid < 2 * DIM) {
        const int d = (tid < DIM) ? tid : tid - DIM;
        const float* src = (tid < DIM) ? sFnP : sFrP;
        float s = 0.f;
        for (int i = 0; i < S; i++) {
            const float2 p = *(const float2*)(src + i * SP + 2 * d);
            s += p.x + p.y;
        }
        smean[tid] = s * (1.0f / (float)S);
    }
    __syncthreads();
    if (tid < DIM) {
        float acc = bg[tid];
        const float* wr = Wg + tid * 2 * DIM;
#pragma unroll 10
        for (int c = 0; c < 2 * DIM; c++) acc = fmaf(wr[c], smean[c], acc);
        const float gg = 1.0f / (1.0f + __expf(-acc));
        sG1[tid] = gg;
        sG2[tid] = 1.0f - gg;
    }

    const float scale = rsqrtf((float)DIM);

    for (int h = 0; h < H; h++) {
        const int pad = h & 3;
        float* o1 = out + ((size_t)(b * H + h) * 124) * DIM;
        float* o2 = o1 + (size_t)S * DIM;

        // W ready (also guards Q/K/S1/S2 reuse)
        cp_wait0();
        __syncthreads();

        // A: dir1 projections  Q = Fn@Wq1^T+b, K = Fr@Wk1^T+b
        wide_tile<0, 0, 0, 9>(sFnP, sW + 0 * WB, pad, mt, g, sQ, sB + 0 * 68);
        wide_tile<0, 0, 0, 9>(sFrP, sW + 1 * WB, pad, mt, g, sK, sB + 1 * 68);
        __syncthreads();

        // B: logits1 -> S1
        mma_tile<1, 1, 1, 1, 9>(sQ, sK, 0, mt, g * 8, sS1, 0, scale);
        __syncthreads();

        // C: softmax1 (in place) + dir2 projections (reuse Q/K)
        softmax62(sS1);
        wide_tile<0, 0, 0, 9>(sFrP, sW + 2 * WB, pad, mt, g, sQ, sB + 2 * 68);
        wide_tile<0, 0, 0, 9>(sFnP, sW + 3 * WB, pad, mt, g, sK, sB + 3 * 68);
        __syncthreads();

        // prefetch next head's weights (all 4 consumed)
        if (h + 1 < H)
            prefetch_head(Wq1, Wk1, Wq2, Wk2, bq1, bk1, bq2, bk2, h + 1, sW, sB);

        // D: logits2 -> S2
        mma_tile<1, 1, 1, 1, 9>(sQ, sK, 0, mt, g * 8, sS2, 0, scale);
        __syncthreads();

        // E: softmax2
        softmax62(sS2);
        __syncthreads();

        // F: loss gram (single-pass) + gated outputs
        float ss = mma_tile<3, 2, 2, 1, 8>(sS1, sS2, 0, mt, g * 8, (float*)0, 0, 0.f);
        wide_tile<2, 1, 3, 8>(sS1, sFrP, 0, mt, g, o1, sG1);
        wide_tile<2, 1, 3, 8>(sS2, sFnP, 0, mt, g, o2, sG2);
#pragma unroll
        for (int off = 16; off; off >>= 1) ss += __shfl_xor_sync(0xffffffffu, ss, off);
        if ((tid & 31) == 0) swarp[w] = ss;
        __syncthreads();
        if (tid == 0) {
            float t = 0.f;
#pragma unroll
            for (int ww = 0; ww < 32; ww++) t += swarp[ww];
            g_norms[b * H + h] = sqrtf(t);
        }
    }
}

__global__ void loss_kernel(float* __restrict__ out_loss)
{
    __shared__ float ws[8];
    const int tid = threadIdx.x;
    float s = 0.f;
    for (int i = tid; i < BSZ * H; i += 256) s += g_norms[i];
#pragma unroll
    for (int off = 16; off; off >>= 1) s += __shfl_xor_sync(0xffffffffu, s, off);
    if ((tid & 31) == 0) ws[tid >> 5] = s;
    __syncthreads();
    if (tid == 0) {
        float t = 0.f;
#pragma unroll
        for (int w = 0; w < 8; w++) t += ws[w];
        *out_loss = t / (float)(BSZ * H);
    }
}

extern "C" void kernel_launch(void* const* d_in, const int* in_sizes, int n_in,
                              void* d_out, int out_size)
{
    const float* Fn  = (const float*)d_in[0];
    const float* Fr  = (const float*)d_in[1];
    const float* Wq1 = (const float*)d_in[2];
    const float* bq1 = (const float*)d_in[3];
    const float* Wk1 = (const float*)d_in[4];
    const float* bk1 = (const float*)d_in[5];
    const float* Wq2 = (const float*)d_in[6];
    const float* bq2 = (const float*)d_in[7];
    const float* Wk2 = (const float*)d_in[8];
    const float* bk2 = (const float*)d_in[9];
    const float* Wg  = (const float*)d_in[10];
    const float* bg  = (const float*)d_in[11];
    float* out = (float*)d_out;

    const int smem_bytes = SMEM_FLOATS * (int)sizeof(float);
    cudaFuncSetAttribute(fused_kernel, cudaFuncAttributeMaxDynamicSharedMemorySize, smem_bytes);
    fused_kernel<<<BSZ, NT, smem_bytes>>>(Fn, Fr, Wq1, bq1, Wk1, bk1,
                                          Wq2, bq2, Wk2, bk2, Wg, bg, out);
    loss_kernel<<<1, 256>>>(out + (size_t)out_size - 1);
}

// round 10
// speedup vs baseline: 2.2493x; 2.2477x over previous
#include <cuda_runtime.h>
#include <cuda_fp16.h>
#include <cstdint>

#define BSZ 1024
#define S 62
#define DIM 65
#define H 10
#define NT 512

// smem word offsets (all operand planes stride 36 words = 72 fp16)
#define W_FNH 0
#define W_FNL 2304
#define W_FRH 4608
#define W_FRL 6912
#define W_TNH 9216
#define W_TNL 11808
#define W_TRH 14400
#define W_TRL 16992
#define W_WH  19584
#define W_WL  24768
#define W_QH  29952
#define W_QL  32256
#define W_KH  34560
#define W_KL  36864
#define W_A1H 39168
#define W_A1L 41472
#define W_A2H 43776
#define W_A2L 46080
#define W_SS  48384
#define W_BIA 52992
#define W_G   55872
#define W_WRP 56016
#define W_FLG 56032
#define SMEM_WORDS 56040   // 224160 B

__device__ uint32_t g_wh[40 * 72 * 36];
__device__ uint32_t g_wl[40 * 72 * 36];
__device__ float    g_gate[BSZ * DIM];
__device__ float    g_norms[BSZ * H];
__device__ int      g_ctr;

__device__ __forceinline__ void cp16(uint32_t dst, const void* src) {
    asm volatile("cp.async.cg.shared.global [%0], [%1], 16;\n" :: "r"(dst), "l"(src));
}
__device__ __forceinline__ void cp_commit() { asm volatile("cp.async.commit_group;\n"); }
__device__ __forceinline__ void cp_wait0()  { asm volatile("cp.async.wait_group 0;\n"); }

__device__ __forceinline__ void pack_hl(float x, float y, uint32_t& hw, uint32_t& lw) {
    const __half hx = __float2half_rn(x), hy = __float2half_rn(y);
    __half2 h = __halves2half2(hx, hy);
    __half2 l = __halves2half2(__float2half_rn(x - __half2float(hx)),
                               __float2half_rn(y - __half2float(hy)));
    hw = *reinterpret_cast<uint32_t*>(&h);
    lw = *reinterpret_cast<uint32_t*>(&l);
}

__device__ __forceinline__ void mma16(float* c, uint32_t a0, uint32_t a1,
                                      uint32_t a2, uint32_t a3, uint32_t b0, uint32_t b1) {
    asm volatile("mma.sync.aligned.m16n8k16.row.col.f32.f16.f16.f32 "
                 "{%0,%1,%2,%3}, {%4,%5,%6,%7}, {%8,%9}, {%0,%1,%2,%3};\n"
                 : "+f"(c[0]), "+f"(c[1]), "+f"(c[2]), "+f"(c[3])
                 : "r"(a0), "r"(a1), "r"(a2), "r"(a3), "r"(b0), "r"(b1));
}
__device__ __forceinline__ void mma8h(float* c, uint32_t a0, uint32_t a1, uint32_t b0) {
    asm volatile("mma.sync.aligned.m16n8k8.row.col.f32.f16.f16.f32 "
                 "{%0,%1,%2,%3}, {%4,%5}, {%6}, {%0,%1,%2,%3};\n"
                 : "+f"(c[0]), "+f"(c[1]), "+f"(c[2]), "+f"(c[3])
                 : "r"(a0), "r"(a1), "r"(b0));
}

// pre-pack all 40 weight mats into [mat][n(72)][kw(36)] hi/lo planes
__global__ void prep_w_kernel(const float* __restrict__ Wq1, const float* __restrict__ Wk1,
                              const float* __restrict__ Wq2, const float* __restrict__ Wk2) {
    const float* srcs[4] = { Wq1, Wk1, Wq2, Wk2 };
    const int total = 40 * 72 * 36;
    for (int idx = blockIdx.x * blockDim.x + threadIdx.x; idx < total;
         idx += gridDim.x * blockDim.x) {
        const int m = idx / (72 * 36);
        const int rem = idx - m * 72 * 36;
        const int n = rem / 36, kw = rem - n * 36;
        const float* src = srcs[m & 3] + (m >> 2) * DIM * DIM;
        const int k0 = 2 * kw, k1 = k0 + 1;
        const float v0 = (n < DIM && k0 < DIM) ? src[n * DIM + k0] : 0.f;
        const float v1 = (n < DIM && k1 < DIM) ? src[n * DIM + k1] : 0.f;
        uint32_t hw, lw;
        pack_hl(v0, v1, hw, lw);
        g_wh[idx] = hw; g_wl[idx] = lw;
    }
}

__global__ void prep_g_kernel(const float* __restrict__ Fn, const float* __restrict__ Fr,
                              const float* __restrict__ Wg, const float* __restrict__ bg) {
    __shared__ float mean[132];
    const int b = blockIdx.x, t = threadIdx.x;
    for (int d = t; d < 2 * DIM; d += 128) {
        const float* src = (d < DIM) ? (Fn + (size_t)b * S * DIM + d)
                                     : (Fr + (size_t)b * S * DIM + d - DIM);
        float s = 0.f;
        for (int i = 0; i < S; i++) s += src[i * DIM];
        mean[d] = s * (1.0f / (float)S);
    }
    __syncthreads();
    if (t < DIM) {
        float acc = bg[t];
        const float* wr = Wg + t * 2 * DIM;
#pragma unroll 10
        for (int c = 0; c < 2 * DIM; c++) acc = fmaf(wr[c], mean[c], acc);
        g_gate[b * DIM + t] = 1.0f / (1.0f + __expf(-acc));
    }
}

// Warp tile over packed planes: A [m][kw], B [n][kw] (both stride 36).
// 3-term split: hh + lh + hl. KS16 = 4 always; K8 adds kw 32..35.
// EPI0: pack into Q planes + bias; EPI1: fp32 scores*scale (stride 72);
// EPI2: gmem gated store; EPI3: return sum (acc-I)^2
template <int EPI, int NS, bool K8>
__device__ __forceinline__ float mma_tile(
    const uint32_t* __restrict__ AH, const uint32_t* __restrict__ AL,
    const uint32_t* __restrict__ BH, const uint32_t* __restrict__ BL,
    const int mt, const int n0, void* c0, void* c1,
    const float* __restrict__ aux, const float scale)
{
    const int lane = threadIdx.x & 31, lr = lane >> 2, lc = lane & 3;
    float acc[NS][4];
#pragma unroll
    for (int ns = 0; ns < NS; ns++)
        acc[ns][0] = acc[ns][1] = acc[ns][2] = acc[ns][3] = 0.f;

    const uint32_t* ah = AH + (mt * 16 + lr) * 36 + lc;
    const uint32_t* al = AL + (mt * 16 + lr) * 36 + lc;

#pragma unroll
    for (int s = 0; s < 4; s++) {
        const int kb = 8 * s;
        const uint32_t h0 = ah[kb], h1 = ah[8 * 36 + kb], h2 = ah[kb + 4], h3 = ah[8 * 36 + kb + 4];
        const uint32_t l0 = al[kb], l1 = al[8 * 36 + kb], l2 = al[kb + 4], l3 = al[8 * 36 + kb + 4];
#pragma unroll
        for (int ns = 0; ns < NS; ns++) {
            const int nb = n0 + ns * 8;
            const uint32_t bh0 = BH[(nb + lr) * 36 + lc + kb], bh1 = BH[(nb + lr) * 36 + lc + kb + 4];
            const uint32_t bl0 = BL[(nb + lr) * 36 + lc + kb], bl1 = BL[(nb + lr) * 36 + lc + kb + 4];
            mma16(acc[ns], h0, h1, h2, h3, bh0, bh1);
            mma16(acc[ns], l0, l1, l2, l3, bh0, bh1);
            mma16(acc[ns], h0, h1, h2, h3, bl0, bl1);
        }
    }
    if (K8) {
        const uint32_t h0 = ah[32], h1 = ah[8 * 36 + 32];
        const uint32_t l0 = al[32], l1 = al[8 * 36 + 32];
#pragma unroll
        for (int ns = 0; ns < NS; ns++) {
            const int nb = n0 + ns * 8;
            const uint32_t bh0 = BH[(nb + lr) * 36 + lc + 32];
            const uint32_t bl0 = BL[(nb + lr) * 36 + lc + 32];
            mma8h(acc[ns], h0, h1, bh0);
            mma8h(acc[ns], l0, l1, bh0);
            mma8h(acc[ns], h0, h1, bl0);
        }
    }

    float ss = 0.f;
    const int r0 = mt * 16 + lr, rr = r0 + 8;
#pragma unroll
    for (int ns = 0; ns < NS; ns++) {
        const int col = n0 + ns * 8 + 2 * lc;
        if (EPI == 0) {
            uint32_t* cH = (uint32_t*)c0;
            uint32_t* cL = (uint32_t*)c1;
            const float b0v = aux[col], b1v = aux[col + 1];
            const int kw = (n0 >> 1) + 4 * ns + lc;
            uint32_t hw, lw;
            pack_hl(acc[ns][0] + b0v, acc[ns][1] + b1v, hw, lw);
            cH[r0 * 36 + kw] = hw; cL[r0 * 36 + kw] = lw;
            pack_hl(acc[ns][2] + b0v, acc[ns][3] + b1v, hw, lw);
            cH[rr * 36 + kw] = hw; cL[rr * 36 + kw] = lw;
        } else if (EPI == 1) {
            float* cS = (float*)c0;
            *(float2*)(cS + r0 * 72 + col) = make_float2(acc[ns][0] * scale, acc[ns][1] * scale);
            *(float2*)(cS + rr * 72 + col) = make_float2(acc[ns][2] * scale, acc[ns][3] * scale);
        } else if (EPI == 2) {
            float* o = (float*)c0;
            if (col < 64) {
                const float ga = aux[col], gb = aux[col + 1];
                o[r0 * DIM + col] = ga * acc[ns][0];
                o[r0 * DIM + col + 1] = gb * acc[ns][1];
                if (rr < S) {
                    o[rr * DIM + col] = ga * acc[ns][2];
                    o[rr * DIM + col + 1] = gb * acc[ns][3];
                }
            } else if (col == 64) {
                o[r0 * DIM + 64] = aux[64] * acc[ns][0];
                if (rr < S) o[rr * DIM + 64] = aux[64] * acc[ns][2];
            }
        } else {
            if (col < S) { const float d = acc[ns][0] - ((r0 == col) ? 1.f : 0.f); ss = fmaf(d, d, ss); }
            if (col + 1 < S) { const float d = acc[ns][1] - ((r0 == col + 1) ? 1.f : 0.f); ss = fmaf(d, d, ss); }
            if (rr < S) {
                if (col < S) { const float d = acc[ns][2] - ((rr == col) ? 1.f : 0.f); ss = fmaf(d, d, ss); }
                if (col + 1 < S) { const float d = acc[ns][3] - ((rr == col + 1) ? 1.f : 0.f); ss = fmaf(d, d, ss); }
            }
        }
    }
    return ss;
}

// 72-wide N dispatch: g 0..2 -> 16 cols each, g==3 -> 24 cols (48..71)
template <int EPI, bool K8>
__device__ __forceinline__ float wide_gemm(
    const uint32_t* AH, const uint32_t* AL, const uint32_t* BH, const uint32_t* BL,
    int mt, int g, void* c0, void* c1, const float* aux)
{
    if (g < 3) return mma_tile<EPI, 2, K8>(AH, AL, BH, BL, mt, g * 16, c0, c1, aux, 0.f);
    return mma_tile<EPI, 3, K8>(AH, AL, BH, BL, mt, 48, c0, c1, aux, 0.f);
}

// softmax rows of sS (fp32, stride 72) -> packed A planes [r][rw]
__device__ __forceinline__ void softmax_pack(const float* __restrict__ sS,
                                             uint32_t* __restrict__ AHp,
                                             uint32_t* __restrict__ ALp) {
    const int w = threadIdx.x >> 5, lane = threadIdx.x & 31;
    const bool ok1 = (lane + 32) < S;
    for (int r = w; r < S; r += 16) {
        const float* row = sS + r * 72;
        const float v0 = row[lane];
        const float v1 = ok1 ? row[lane + 32] : -1e30f;
        float m = fmaxf(v0, v1);
#pragma unroll
        for (int off = 16; off; off >>= 1) m = fmaxf(m, __shfl_xor_sync(0xffffffffu, m, off));
        const float e0 = __expf(v0 - m);
        const float e1 = ok1 ? __expf(v1 - m) : 0.f;
        float s = e0 + e1;
#pragma unroll
        for (int off = 16; off; off >>= 1) s += __shfl_xor_sync(0xffffffffu, s, off);
        const float inv = 1.0f / s;
        const float p0 = e0 * inv, p1 = ok1 ? e1 * inv : 0.f;
        const float p0n = __shfl_down_sync(0xffffffffu, p0, 1);
        const float p1n = __shfl_down_sync(0xffffffffu, p1, 1);
        if ((lane & 1) == 0) {
            uint32_t hw, lw;
            pack_hl(p0, p0n, hw, lw);
            AHp[r * 36 + (lane >> 1)] = hw; ALp[r * 36 + (lane >> 1)] = lw;
            pack_hl(p1, p1n, hw, lw);
            AHp[r * 36 + (lane >> 1) + 16] = hw; ALp[r * 36 + (lane >> 1) + 16] = lw;
        }
    }
}

// stream one direction's 2 packed mats (hi+lo), 16B aligned
__device__ __forceinline__ void prefetch_wdir(int h, int d, uint32_t* sWH, uint32_t* sWL) {
    const int base = (h * 4 + 2 * d) * 2592;
    const float4* sh = (const float4*)(g_wh + base);
    const float4* sl = (const float4*)(g_wl + base);
    const uint32_t dh = (uint32_t)__cvta_generic_to_shared(sWH);
    const uint32_t dl = (uint32_t)__cvta_generic_to_shared(sWL);
    for (int j = threadIdx.x; j < 1296; j += NT) {
        cp16(dh + 16u * j, sh + j);
        cp16(dl + 16u * j, sl + j);
    }
    cp_commit();
}

__global__ void __launch_bounds__(NT, 1)
fused_kernel(const float* __restrict__ Fn, const float* __restrict__ Fr,
             const float* __restrict__ bq1, const float* __restrict__ bk1,
             const float* __restrict__ bq2, const float* __restrict__ bk2,
             float* __restrict__ out, float* __restrict__ out_loss)
{
    extern __shared__ uint32_t sm[];
    const int tid = threadIdx.x, b = blockIdx.x, w = tid >> 5;
    const int mt = w & 3, g = w >> 2;
    float* sS = (float*)(sm + W_SS);
    float* sBias = (float*)(sm + W_BIA);
    float* sG = (float*)(sm + W_G);
    float* swarp = (float*)(sm + W_WRP);
    int* sflag = (int*)(sm + W_FLG);

    {   // zero all smem once: every pad is a hard zero
        float4* z = (float4*)sm;
        const float4 z4 = make_float4(0.f, 0.f, 0.f, 0.f);
        for (int i = tid; i < SMEM_WORDS / 4; i += NT) z[i] = z4;
    }
    __syncthreads();
    prefetch_wdir(0, 0, sm + W_WH, sm + W_WL);

    const float* fn = Fn + (size_t)b * S * DIM;
    const float* fr = Fr + (size_t)b * S * DIM;
    for (int idx = tid; idx < S * 33; idx += NT) {   // d-packed (A-role)
        const int r = idx / 33, kw = idx - r * 33;
        const int k0 = 2 * kw, k1 = k0 + 1;
        uint32_t hw, lw;
        pack_hl(fn[r * DIM + k0], (k1 < DIM) ? fn[r * DIM + k1] : 0.f, hw, lw);
        sm[W_FNH + r * 36 + kw] = hw; sm[W_FNL + r * 36 + kw] = lw;
        pack_hl(fr[r * DIM + k0], (k1 < DIM) ? fr[r * DIM + k1] : 0.f, hw, lw);
        sm[W_FRH + r * 36 + kw] = hw; sm[W_FRL + r * 36 + kw] = lw;
    }
    for (int idx = tid; idx < DIM * 31; idx += NT) { // r-packed (B-role)
        const int d = idx / 31, rw = idx - d * 31;
        const int r0i = 2 * rw, r1i = r0i + 1;
        uint32_t hw, lw;
        pack_hl(fn[r0i * DIM + d], fn[r1i * DIM + d], hw, lw);
        sm[W_TNH + d * 36 + rw] = hw; sm[W_TNL + d * 36 + rw] = lw;
        pack_hl(fr[r0i * DIM + d], fr[r1i * DIM + d], hw, lw);
        sm[W_TRH + d * 36 + rw] = hw; sm[W_TRL + d * 36 + rw] = lw;
    }
    {
        const float* bsrc[4] = { bq1, bk1, bq2, bk2 };
        for (int idx = tid; idx < 40 * DIM; idx += NT) {
            const int m = idx / DIM, o = idx - m * DIM;
            sBias[m * 72 + o] = bsrc[m & 3][(m >> 2) * DIM + o];
        }
    }
    if (tid < DIM) {
        const float gg = g_gate[b * DIM + tid];
        sG[tid] = gg; sG[72 + tid] = 1.0f - gg;
    }
    const float scale = rsqrtf((float)DIM);

    for (int h = 0; h < H; h++) {
        float* o1 = out + ((size_t)(b * H + h) * 124) * DIM;
        float* o2 = o1 + (size_t)S * DIM;
        cp_wait0();
        __syncthreads();
        // dir1 projections
        wide_gemm<0, true>(sm + W_FNH, sm + W_FNL, sm + W_WH, sm + W_WL, mt, g,
                           sm + W_QH, sm + W_QL, sBias + (h * 4 + 0) * 72);
        wide_gemm<0, true>(sm + W_FRH, sm + W_FRL, sm + W_WH + 2592, sm + W_WL + 2592, mt, g,
                           sm + W_KH, sm + W_KL, sBias + (h * 4 + 1) * 72);
        __syncthreads();
        // refill W with dir2; logits1
        prefetch_wdir(h, 1, sm + W_WH, sm + W_WL);
        mma_tile<1, 2, true>(sm + W_QH, sm + W_QL, sm + W_KH, sm + W_KL, mt, g * 16, sS, 0, 0, scale);
        __syncthreads();
        softmax_pack(sS, sm + W_A1H, sm + W_A1L);
        cp_wait0();
        __syncthreads();
        // dir2 projections
        wide_gemm<0, true>(sm + W_FRH, sm + W_FRL, sm + W_WH, sm + W_WL, mt, g,
                           sm + W_QH, sm + W_QL, sBias + (h * 4 + 2) * 72);
        wide_gemm<0, true>(sm + W_FNH, sm + W_FNL, sm + W_WH + 2592, sm + W_WL + 2592, mt, g,
                           sm + W_KH, sm + W_KL, sBias + (h * 4 + 3) * 72);
        __syncthreads();
        if (h + 1 < H) prefetch_wdir(h + 1, 0, sm + W_WH, sm + W_WL);
        mma_tile<1, 2, true>(sm + W_QH, sm + W_QL, sm + W_KH, sm + W_KL, mt, g * 16, sS, 0, 0, scale);
        __syncthreads();
        softmax_pack(sS, sm + W_A2H, sm + W_A2L);
        __syncthreads();
        // loss gram + gated outputs
        float ss = mma_tile<3, 2, false>(sm + W_A1H, sm + W_A1L, sm + W_A2H, sm + W_A2L,
                                         mt, g * 16, 0, 0, 0, 0.f);
        wide_gemm<2, false>(sm + W_A1H, sm + W_A1L, sm + W_TRH, sm + W_TRL, mt, g, o1, 0, sG);
        wide_gemm<2, false>(sm + W_A2H, sm + W_A2L, sm + W_TNH, sm + W_TNL, mt, g, o2, 0, sG + 72);
#pragma unroll
        for (int off = 16; off; off >>= 1) ss += __shfl_xor_sync(0xffffffffu, ss, off);
        if ((tid & 31) == 0) swarp[w] = ss;
        __syncthreads();
        if (tid == 0) {
            float t = 0.f;
#pragma unroll
            for (int ww = 0; ww < 16; ww++) t += swarp[ww];
            g_norms[b * H + h] = sqrtf(t);
        }
    }

    // merged deterministic loss reduction: last CTA of each replay reduces
    __threadfence();
    __syncthreads();
    if (tid == 0) *sflag = ((atomicAdd(&g_ctr, 1) % BSZ) == BSZ - 1) ? 1 : 0;
    __syncthreads();
    if (*sflag) {
        float s = 0.f;
        for (int i = tid; i < BSZ * H; i += NT) s += g_norms[i];
#pragma unroll
        for (int off = 16; off; off >>= 1) s += __shfl_xor_sync(0xffffffffu, s, off);
        if ((tid & 31) == 0) swarp[w] = s;
        __syncthreads();
        if (tid == 0) {
            float t = 0.f;
#pragma unroll
            for (int ww = 0; ww < 16; ww++) t += swarp[ww];
            *out_loss = t / (float)(BSZ * H);
        }
    }
}

extern "C" void kernel_launch(void* const* d_in, const int* in_sizes, int n_in,
                              void* d_out, int out_size)
{
    const float* Fn  = (const float*)d_in[0];
    const float* Fr  = (const float*)d_in[1];
    const float* Wq1 = (const float*)d_in[2];
    const float* bq1 = (const float*)d_in[3];
    const float* Wk1 = (const float*)d_in[4];
    const float* bk1 = (const float*)d_in[5];
    const float* Wq2 = (const float*)d_in[6];
    const float* bq2 = (const float*)d_in[7];
    const float* Wk2 = (const float*)d_in[8];
    const float* bk2 = (const float*)d_in[9];
    const float* Wg  = (const float*)d_in[10];
    const float* bg  = (const float*)d_in[11];
    float* out = (float*)d_out;

    prep_w_kernel<<<160, 256>>>(Wq1, Wk1, Wq2, Wk2);
    prep_g_kernel<<<BSZ, 128>>>(Fn, Fr, Wg, bg);
    const int smem_bytes = SMEM_WORDS * 4;
    cudaFuncSetAttribute(fused_kernel, cudaFuncAttributeMaxDynamicSharedMemorySize, smem_bytes);
    fused_kernel<<<BSZ, NT, smem_bytes>>>(Fn, Fr, bq1, bk1, bq2, bk2,
                                          out, out + (size_t)out_size - 1);
}

// round 11
// speedup vs baseline: 2.2859x; 1.0163x over previous
#include <cuda_runtime.h>
#include <cuda_fp16.h>
#include <cstdint>

#define BSZ 1024
#define S 62
#define DIM 65
#define H 10
#define NT 512

#define W_FNH 0
#define W_FNL 2304
#define W_FRH 4608
#define W_FRL 6912
#define W_TNH 9216
#define W_TNL 11808
#define W_TRH 14400
#define W_TRL 16992
#define W_WH  19584
#define W_WL  24768
#define W_QH  29952
#define W_QL  32256
#define W_KH  34560
#define W_KL  36864
#define W_A1H 39168
#define W_A1L 41472
#define W_A2H 43776
#define W_A2L 46080
#define W_SS  48384
#define W_BIA 52992
#define W_G   55872
#define W_WRP 56016
#define W_FLG 56032
#define SMEM_WORDS 56040

__device__ uint32_t g_wh[40 * 72 * 36];
__device__ uint32_t g_wl[40 * 72 * 36];
__device__ float    g_gate[BSZ * DIM];
__device__ float    g_norms[BSZ * H];
__device__ int      g_ctr;

__device__ __forceinline__ void cp16(uint32_t dst, const void* src) {
    asm volatile("cp.async.cg.shared.global [%0], [%1], 16;\n" :: "r"(dst), "l"(src));
}
__device__ __forceinline__ void cp_commit() { asm volatile("cp.async.commit_group;\n"); }
__device__ __forceinline__ void cp_wait0()  { asm volatile("cp.async.wait_group 0;\n"); }

__device__ __forceinline__ void pack_hl(float x, float y, uint32_t& hw, uint32_t& lw) {
    const __half hx = __float2half_rn(x), hy = __float2half_rn(y);
    __half2 h = __halves2half2(hx, hy);
    __half2 l = __halves2half2(__float2half_rn(x - __half2float(hx)),
                               __float2half_rn(y - __half2float(hy)));
    hw = *reinterpret_cast<uint32_t*>(&h);
    lw = *reinterpret_cast<uint32_t*>(&l);
}

__device__ __forceinline__ void mma16(float* c, uint32_t a0, uint32_t a1,
                                      uint32_t a2, uint32_t a3, uint32_t b0, uint32_t b1) {
    asm volatile("mma.sync.aligned.m16n8k16.row.col.f32.f16.f16.f32 "
                 "{%0,%1,%2,%3}, {%4,%5,%6,%7}, {%8,%9}, {%0,%1,%2,%3};\n"
                 : "+f"(c[0]), "+f"(c[1]), "+f"(c[2]), "+f"(c[3])
                 : "r"(a0), "r"(a1), "r"(a2), "r"(a3), "r"(b0), "r"(b1));
}
__device__ __forceinline__ void mma8h(float* c, uint32_t a0, uint32_t a1, uint32_t b0) {
    asm volatile("mma.sync.aligned.m16n8k8.row.col.f32.f16.f16.f32 "
                 "{%0,%1,%2,%3}, {%4,%5}, {%6}, {%0,%1,%2,%3};\n"
                 : "+f"(c[0]), "+f"(c[1]), "+f"(c[2]), "+f"(c[3])
                 : "r"(a0), "r"(a1), "r"(b0));
}
__device__ __forceinline__ void ldsm4(uint32_t& r0, uint32_t& r1, uint32_t& r2,
                                      uint32_t& r3, uint32_t a) {
    asm volatile("ldmatrix.sync.aligned.m8n8.x4.shared.b16 {%0,%1,%2,%3}, [%4];\n"
                 : "=r"(r0), "=r"(r1), "=r"(r2), "=r"(r3) : "r"(a));
}
__device__ __forceinline__ void ldsm2(uint32_t& r0, uint32_t& r1, uint32_t a) {
    asm volatile("ldmatrix.sync.aligned.m8n8.x2.shared.b16 {%0,%1}, [%2];\n"
                 : "=r"(r0), "=r"(r1) : "r"(a));
}
__device__ __forceinline__ uint32_t s2u(const void* p) {
    return (uint32_t)__cvta_generic_to_shared(p);
}

// merged prep: blocks <BSZ compute gate, blocks >=BSZ pack weights
__global__ void prep_kernel(const float* __restrict__ Fn, const float* __restrict__ Fr,
                            const float* __restrict__ Wg, const float* __restrict__ bg,
                            const float* __restrict__ Wq1, const float* __restrict__ Wk1,
                            const float* __restrict__ Wq2, const float* __restrict__ Wk2) {
    const int t = threadIdx.x;
    if (blockIdx.x < BSZ) {
        __shared__ float mean[132];
        const int b = blockIdx.x;
        if (t < 2 * DIM) {
            const float* src = (t < DIM) ? (Fn + (size_t)b * S * DIM + t)
                                         : (Fr + (size_t)b * S * DIM + t - DIM);
            float s = 0.f;
            for (int i = 0; i < S; i++) s += src[i * DIM];
            mean[t] = s * (1.0f / (float)S);
        }
        __syncthreads();
        if (t < DIM) {
            float acc = bg[t];
            const float* wr = Wg + t * 2 * DIM;
#pragma unroll 10
            for (int c = 0; c < 2 * DIM; c++) acc = fmaf(wr[c], mean[c], acc);
            g_gate[b * DIM + t] = 1.0f / (1.0f + __expf(-acc));
        }
    } else {
        const float* srcs[4] = { Wq1, Wk1, Wq2, Wk2 };
        const int total = 40 * 72 * 36;
        for (int idx = (blockIdx.x - BSZ) * 256 + t; idx < total; idx += 160 * 256) {
            const int m = idx / (72 * 36);
            const int rem = idx - m * 72 * 36;
            const int n = rem / 36, kw = rem - n * 36;
            const float* src = srcs[m & 3] + (m >> 2) * DIM * DIM;
            const int k0 = 2 * kw, k1 = k0 + 1;
            const float v0 = (n < DIM && k0 < DIM) ? src[n * DIM + k0] : 0.f;
            const float v1 = (n < DIM && k1 < DIM) ? src[n * DIM + k1] : 0.f;
            uint32_t hw, lw;
            pack_hl(v0, v1, hw, lw);
            g_wh[idx] = hw; g_wl[idx] = lw;
        }
    }
}

// Warp tile over packed planes via ldmatrix. A [m][kw], B [n][kw], stride 36.
// EPI0: pack+bias into Q planes; EPI1: fp32 scores*scale; EPI2: gmem gated; EPI3: loss
template <int EPI, int NS, bool K8>
__device__ __forceinline__ float mma_tile(
    const uint32_t* __restrict__ AH, const uint32_t* __restrict__ AL,
    const uint32_t* __restrict__ BH, const uint32_t* __restrict__ BL,
    const int mt, const int n0, void* c0, void* c1,
    const float* __restrict__ aux, const float scale)
{
    const int lane = threadIdx.x & 31, lr = lane >> 2, lc = lane & 3;
    float acc[NS][4];
#pragma unroll
    for (int ns = 0; ns < NS; ns++)
        acc[ns][0] = acc[ns][1] = acc[ns][2] = acc[ns][3] = 0.f;

    // ldmatrix lane addressing
    const int ar = lane & 15, ac4 = (lane >> 4) << 2;
    const int br = (lane & 7) | ((lane >> 4) << 3), bc4 = ((lane >> 3) & 1) << 2;
    const uint32_t aH = s2u(AH) + (((mt * 16 + ar) * 36 + ac4) << 2);
    const uint32_t aL = s2u(AL) + (((mt * 16 + ar) * 36 + ac4) << 2);
    const uint32_t bH = s2u(BH) + (((n0 + br) * 36 + bc4) << 2);
    const uint32_t bL = s2u(BL) + (((n0 + br) * 36 + bc4) << 2);
    const int xr = n0 + 16 + (lane & 7), xc4 = ((lane >> 3) & 1) << 2;
    const uint32_t bHx = s2u(BH) + ((xr * 36 + xc4) << 2);
    const uint32_t bLx = s2u(BL) + ((xr * 36 + xc4) << 2);

#pragma unroll
    for (int s = 0; s < 4; s++) {
        const uint32_t kb = 32u * s;
        uint32_t a0, a1, a2, a3, e0, e1, e2, e3;
        ldsm4(a0, a1, a2, a3, aH + kb);
        ldsm4(e0, e1, e2, e3, aL + kb);
        uint32_t b0, b1, b2, b3, f0, f1, f2, f3;
        ldsm4(b0, b1, b2, b3, bH + kb);
        ldsm4(f0, f1, f2, f3, bL + kb);
        mma16(acc[0], a0, a1, a2, a3, b0, b1);
        mma16(acc[0], e0, e1, e2, e3, b0, b1);
        mma16(acc[0], a0, a1, a2, a3, f0, f1);
        if (NS > 1) {
            mma16(acc[1], a0, a1, a2, a3, b2, b3);
            mma16(acc[1], e0, e1, e2, e3, b2, b3);
            mma16(acc[1], a0, a1, a2, a3, f2, f3);
        }
        if (NS > 2) {
            uint32_t x0, x1, y0, y1;
            ldsm2(x0, x1, bHx + kb);
            ldsm2(y0, y1, bLx + kb);
            mma16(acc[2], a0, a1, a2, a3, x0, x1);
            mma16(acc[2], e0, e1, e2, e3, x0, x1);
            mma16(acc[2], a0, a1, a2, a3, y0, y1);
        }
    }
    if (K8) {  // kw 32..35 tail, scalar
        const uint32_t* ah = AH + (mt * 16 + lr) * 36 + lc;
        const uint32_t* al = AL + (mt * 16 + lr) * 36 + lc;
        const uint32_t h0 = ah[32], h1 = ah[8 * 36 + 32];
        const uint32_t l0 = al[32], l1 = al[8 * 36 + 32];
#pragma unroll
        for (int ns = 0; ns < NS; ns++) {
            const int nb = n0 + ns * 8;
            const uint32_t p = BH[(nb + lr) * 36 + lc + 32];
            const uint32_t q = BL[(nb + lr) * 36 + lc + 32];
            mma8h(acc[ns], h0, h1, p);
            mma8h(acc[ns], l0, l1, p);
            mma8h(acc[ns], h0, h1, q);
        }
    }

    float ss = 0.f;
    const int r0 = mt * 16 + lr, rr = r0 + 8;
#pragma unroll
    for (int ns = 0; ns < NS; ns++) {
        const int col = n0 + ns * 8 + 2 * lc;
        if (EPI == 0) {
            uint32_t* cH = (uint32_t*)c0;
            uint32_t* cL = (uint32_t*)c1;
            const float b0v = aux[col], b1v = aux[col + 1];
            const int kw = (n0 >> 1) + 4 * ns + lc;
            uint32_t hw, lw;
            pack_hl(acc[ns][0] + b0v, acc[ns][1] + b1v, hw, lw);
            cH[r0 * 36 + kw] = hw; cL[r0 * 36 + kw] = lw;
            pack_hl(acc[ns][2] + b0v, acc[ns][3] + b1v, hw, lw);
            cH[rr * 36 + kw] = hw; cL[rr * 36 + kw] = lw;
        } else if (EPI == 1) {
            float* cS = (float*)c0;
            *(float2*)(cS + r0 * 72 + col) = make_float2(acc[ns][0] * scale, acc[ns][1] * scale);
            *(float2*)(cS + rr * 72 + col) = make_float2(acc[ns][2] * scale, acc[ns][3] * scale);
        } else if (EPI == 2) {
            float* o = (float*)c0;
            if (col < 64) {
                const float ga = aux[col], gb = aux[col + 1];
                o[r0 * DIM + col] = ga * acc[ns][0];
                o[r0 * DIM + col + 1] = gb * acc[ns][1];
                if (rr < S) {
                    o[rr * DIM + col] = ga * acc[ns][2];
                    o[rr * DIM + col + 1] = gb * acc[ns][3];
                }
            } else if (col == 64) {
                o[r0 * DIM + 64] = aux[64] * acc[ns][0];
                if (rr < S) o[rr * DIM + 64] = aux[64] * acc[ns][2];
            }
        } else {
            if (col < S) { const float d = acc[ns][0] - ((r0 == col) ? 1.f : 0.f); ss = fmaf(d, d, ss); }
            if (col + 1 < S) { const float d = acc[ns][1] - ((r0 == col + 1) ? 1.f : 0.f); ss = fmaf(d, d, ss); }
            if (rr < S) {
                if (col < S) { const float d = acc[ns][2] - ((rr == col) ? 1.f : 0.f); ss = fmaf(d, d, ss); }
                if (col + 1 < S) { const float d = acc[ns][3] - ((rr == col + 1) ? 1.f : 0.f); ss = fmaf(d, d, ss); }
            }
        }
    }
    return ss;
}

template <int EPI, bool K8>
__device__ __forceinline__ float wide_gemm(
    const uint32_t* AH, const uint32_t* AL, const uint32_t* BH, const uint32_t* BL,
    int mt, int g, void* c0, void* c1, const float* aux)
{
    if (g < 3) return mma_tile<EPI, 2, K8>(AH, AL, BH, BL, mt, g * 16, c0, c1, aux, 0.f);
    return mma_tile<EPI, 3, K8>(AH, AL, BH, BL, mt, 48, c0, c1, aux, 0.f);
}

__device__ __forceinline__ void softmax_pack(const float* __restrict__ sS,
                                             uint32_t* __restrict__ AHp,
                                             uint32_t* __restrict__ ALp) {
    const int w = threadIdx.x >> 5, lane = threadIdx.x & 31;
    const bool ok1 = (lane + 32) < S;
    for (int r = w; r < S; r += 16) {
        const float* row = sS + r * 72;
        const float v0 = row[lane];
        const float v1 = ok1 ? row[lane + 32] : -1e30f;
        float m = fmaxf(v0, v1);
#pragma unroll
        for (int off = 16; off; off >>= 1) m = fmaxf(m, __shfl_xor_sync(0xffffffffu, m, off));
        const float e0 = __expf(v0 - m);
        const float e1 = ok1 ? __expf(v1 - m) : 0.f;
        float s = e0 + e1;
#pragma unroll
        for (int off = 16; off; off >>= 1) s += __shfl_xor_sync(0xffffffffu, s, off);
        const float inv = 1.0f / s;
        const float p0 = e0 * inv, p1 = ok1 ? e1 * inv : 0.f;
        const float p0n = __shfl_down_sync(0xffffffffu, p0, 1);
        const float p1n = __shfl_down_sync(0xffffffffu, p1, 1);
        if ((lane & 1) == 0) {
            uint32_t hw, lw;
            pack_hl(p0, p0n, hw, lw);
            AHp[r * 36 + (lane >> 1)] = hw; ALp[r * 36 + (lane >> 1)] = lw;
            pack_hl(p1, p1n, hw, lw);
            AHp[r * 36 + (lane >> 1) + 16] = hw; ALp[r * 36 + (lane >> 1) + 16] = lw;
        }
    }
}

__device__ __forceinline__ void prefetch_wdir(int h, int d, uint32_t* sWH, uint32_t* sWL) {
    const int base = (h * 4 + 2 * d) * 2592;
    const float4* sh = (const float4*)(g_wh + base);
    const float4* sl = (const float4*)(g_wl + base);
    const uint32_t dh = s2u(sWH), dl = s2u(sWL);
    for (int j = threadIdx.x; j < 1296; j += NT) {
        cp16(dh + 16u * j, sh + j);
        cp16(dl + 16u * j, sl + j);
    }
    cp_commit();
}

__global__ void __launch_bounds__(NT, 1)
fused_kernel(const float* __restrict__ Fn, const float* __restrict__ Fr,
             const float* __restrict__ bq1, const float* __restrict__ bk1,
             const float* __restrict__ bq2, const float* __restrict__ bk2,
             float* __restrict__ out, float* __restrict__ out_loss)
{
    extern __shared__ uint32_t sm[];
    const int tid = threadIdx.x, b = blockIdx.x, w = tid >> 5;
    const int mt = w & 3, g = w >> 2;
    float* sS = (float*)(sm + W_SS);
    float* sBias = (float*)(sm + W_BIA);
    float* sG = (float*)(sm + W_G);
    float* swarp = (float*)(sm + W_WRP);
    int* sflag = (int*)(sm + W_FLG);

    {
        float4* z = (float4*)sm;
        const float4 z4 = make_float4(0.f, 0.f, 0.f, 0.f);
        for (int i = tid; i < SMEM_WORDS / 4; i += NT) z[i] = z4;
    }
    __syncthreads();
    prefetch_wdir(0, 0, sm + W_WH, sm + W_WL);

    const float* fn = Fn + (size_t)b * S * DIM;
    const float* fr = Fr + (size_t)b * S * DIM;
    for (int idx = tid; idx < S * 33; idx += NT) {
        const int r = idx / 33, kw = idx - r * 33;
        const int k0 = 2 * kw, k1 = k0 + 1;
        uint32_t hw, lw;
        pack_hl(fn[r * DIM + k0], (k1 < DIM) ? fn[r * DIM + k1] : 0.f, hw, lw);
        sm[W_FNH + r * 36 + kw] = hw; sm[W_FNL + r * 36 + kw] = lw;
        pack_hl(fr[r * DIM + k0], (k1 < DIM) ? fr[r * DIM + k1] : 0.f, hw, lw);
        sm[W_FRH + r * 36 + kw] = hw; sm[W_FRL + r * 36 + kw] = lw;
    }
    for (int idx = tid; idx < DIM * 31; idx += NT) {
        const int d = idx / 31, rw = idx - d * 31;
        const int r0i = 2 * rw, r1i = r0i + 1;
        uint32_t hw, lw;
        pack_hl(fn[r0i * DIM + d], fn[r1i * DIM + d], hw, lw);
        sm[W_TNH + d * 36 + rw] = hw; sm[W_TNL + d * 36 + rw] = lw;
        pack_hl(fr[r0i * DIM + d], fr[r1i * DIM + d], hw, lw);
        sm[W_TRH + d * 36 + rw] = hw; sm[W_TRL + d * 36 + rw] = lw;
    }
    {
        const float* bsrc[4] = { bq1, bk1, bq2, bk2 };
        for (int idx = tid; idx < 40 * DIM; idx += NT) {
            const int m = idx / DIM, o = idx - m * DIM;
            sBias[m * 72 + o] = bsrc[m & 3][(m >> 2) * DIM + o];
        }
    }
    if (tid < DIM) {
        const float gg = g_gate[b * DIM + tid];
        sG[tid] = gg; sG[72 + tid] = 1.0f - gg;
    }
    const float scale = rsqrtf((float)DIM);

    for (int h = 0; h < H; h++) {
        float* o1 = out + ((size_t)(b * H + h) * 124) * DIM;
        float* o2 = o1 + (size_t)S * DIM;
        cp_wait0();
        __syncthreads();
        wide_gemm<0, true>(sm + W_FNH, sm + W_FNL, sm + W_WH, sm + W_WL, mt, g,
                           sm + W_QH, sm + W_QL, sBias + (h * 4 + 0) * 72);
        wide_gemm<0, true>(sm + W_FRH, sm + W_FRL, sm + W_WH + 2592, sm + W_WL + 2592, mt, g,
                           sm + W_KH, sm + W_KL, sBias + (h * 4 + 1) * 72);
        __syncthreads();
        prefetch_wdir(h, 1, sm + W_WH, sm + W_WL);
        mma_tile<1, 2, true>(sm + W_QH, sm + W_QL, sm + W_KH, sm + W_KL, mt, g * 16, sS, 0, 0, scale);
        __syncthreads();
        softmax_pack(sS, sm + W_A1H, sm + W_A1L);
        cp_wait0();
        __syncthreads();
        wide_gemm<0, true>(sm + W_FRH, sm + W_FRL, sm + W_WH, sm + W_WL, mt, g,
                           sm + W_QH, sm + W_QL, sBias + (h * 4 + 2) * 72);
        wide_gemm<0, true>(sm + W_FNH, sm + W_FNL, sm + W_WH + 2592, sm + W_WL + 2592, mt, g,
                           sm + W_KH, sm + W_KL, sBias + (h * 4 + 3) * 72);
        __syncthreads();
        if (h + 1 < H) prefetch_wdir(h + 1, 0, sm + W_WH, sm + W_WL);
        mma_tile<1, 2, true>(sm + W_QH, sm + W_QL, sm + W_KH, sm + W_KL, mt, g * 16, sS, 0, 0, scale);
        __syncthreads();
        softmax_pack(sS, sm + W_A2H, sm + W_A2L);
        __syncthreads();
        float ss = mma_tile<3, 2, false>(sm + W_A1H, sm + W_A1L, sm + W_A2H, sm + W_A2L,
                                         mt, g * 16, 0, 0, 0, 0.f);
        wide_gemm<2, false>(sm + W_A1H, sm + W_A1L, sm + W_TRH, sm + W_TRL, mt, g, o1, 0, sG);
        wide_gemm<2, false>(sm + W_A2H, sm + W_A2L, sm + W_TNH, sm + W_TNL, mt, g, o2, 0, sG + 72);
#pragma unroll
        for (int off = 16; off; off >>= 1) ss += __shfl_xor_sync(0xffffffffu, ss, off);
        if ((tid & 31) == 0) swarp[w] = ss;
        __syncthreads();
        if (tid == 0) {
            float t = 0.f;
#pragma unroll
            for (int ww = 0; ww < 16; ww++) t += swarp[ww];
            g_norms[b * H + h] = sqrtf(t);
        }
    }

    __threadfence();
    __syncthreads();
    if (tid == 0) *sflag = ((atomicAdd(&g_ctr, 1) % BSZ) == BSZ - 1) ? 1 : 0;
    __syncthreads();
    if (*sflag) {
        float s = 0.f;
        for (int i = tid; i < BSZ * H; i += NT) s += g_norms[i];
#pragma unroll
        for (int off = 16; off; off >>= 1) s += __shfl_xor_sync(0xffffffffu, s, off);
        if ((tid & 31) == 0) swarp[w] = s;
        __syncthreads();
        if (tid == 0) {
            float t = 0.f;
#pragma unroll
            for (int ww = 0; ww < 16; ww++) t += swarp[ww];
            *out_loss = t / (float)(BSZ * H);
        }
    }
}

extern "C" void kernel_launch(void* const* d_in, const int* in_sizes, int n_in,
                              void* d_out, int out_size)
{
    const float* Fn  = (const float*)d_in[0];
    const float* Fr  = (const float*)d_in[1];
    const float* Wq1 = (const float*)d_in[2];
    const float* bq1 = (const float*)d_in[3];
    const float* Wk1 = (const float*)d_in[4];
    const float* bk1 = (const float*)d_in[5];
    const float* Wq2 = (const float*)d_in[6];
    const float* bq2 = (const float*)d_in[7];
    const float* Wk2 = (const float*)d_in[8];
    const float* bk2 = (const float*)d_in[9];
    const float* Wg  = (const float*)d_in[10];
    const float* bg  = (const float*)d_in[11];
    float* out = (float*)d_out;

    prep_kernel<<<BSZ + 160, 256>>>(Fn, Fr, Wg, bg, Wq1, Wk1, Wq2, Wk2);
    const int smem_bytes = SMEM_WORDS * 4;
    cudaFuncSetAttribute(fused_kernel, cudaFuncAttributeMaxDynamicSharedMemorySize, smem_bytes);
    fused_kernel<<<BSZ, NT, smem_bytes>>>(Fn, Fr, bq1, bk1, bq2, bk2,
                                          out, out + (size_t)out_size - 1);
}